// round 8
// baseline (speedup 1.0000x reference)
#include <cuda_runtime.h>
#include <cstdint>

#define NSEG   512
#define HID    512
#define GOALD  128
#define INDIM  640
#define BLOCK  256
#define MROWS  256          // nodes per block
#define KT     16           // k tile (floats)
#define XPAD   20           // padded row stride (words): conflict-free LDS/STS
#define NTILES (INDIM / KT) // 40
#define BUFW   (MROWS * XPAD)
#define WS_OFF (2 * BUFW)
#define SMEM_BYTES ((2 * BUFW + INDIM * 16) * 4)   // ~81 KB

typedef unsigned long long u64;

__device__ float    g_sum[NSEG];
__device__ float    g_cnt[NSEG];
__device__ unsigned g_max[NSEG];
__device__ unsigned g_done;

__device__ __forceinline__ void ffma2(u64 &acc, u64 a, u64 b) {
    asm("fma.rn.f32x2 %0, %1, %2, %0;" : "+l"(acc) : "l"(a), "l"(b));
}
__device__ __forceinline__ u64 pk2(float v) {
    u64 r; asm("mov.b64 %0, {%1, %1};" : "=l"(r) : "f"(v)); return r;
}
__device__ __forceinline__ float2 upk(u64 v) {
    float2 f; asm("mov.b64 {%0, %1}, %2;" : "=f"(f.x), "=f"(f.y) : "l"(v)); return f;
}

__global__ __launch_bounds__(BLOCK, 2) void mlp_seg_kernel(
    const float* __restrict__ nodes, const float* __restrict__ goal,
    const int* __restrict__ segids,
    const float* __restrict__ W1, const float* __restrict__ b1,
    const float* __restrict__ W2, const float* __restrict__ b2,
    float* __restrict__ out, int N, int grid)
{
    extern __shared__ float smem[];
    float* ws = smem + WS_OFF;           // [INDIM][16]
    const int t    = threadIdx.x;
    const int base = blockIdx.x * MROWS;
    const int lane = t & 31, warp = t >> 5;
    const int jh   = t >> 7;             // j-half: 0 -> j0..7, 1 -> j8..15
    const int row0 = t & 127;            // node rows: row0, row0+128

    // --- preload full W1 (10240 floats, coalesced) ---
#pragma unroll
    for (int p = 0; p < INDIM * 16 / 4 / BLOCK; ++p)
        ((float4*)ws)[p * BLOCK + t] = ((const float4*)W1)[p * BLOCK + t];

    // --- staging mapping: conflict-free STS, coalesced LDG ---
    // row = warp*8 + (lane&7) (+64 per pass), quarter = lane>>3 (16B each)
    const int srow = (warp << 3) + (lane & 7);   // 0..63
    const int qofs = (lane >> 3) * 4;            // float offset within 16-float row

    auto ldg_tile = [&](int tile, float4* v) {
        const int k0 = tile * KT;
        const float* src; int stride, kloc;
        if (k0 < HID) { src = nodes; stride = HID;   kloc = k0; }
        else          { src = goal;  stride = GOALD; kloc = k0 - HID; }
#pragma unroll
        for (int pass = 0; pass < 4; ++pass) {
            int node = base + pass * 64 + srow;
            v[pass] = (node < N)
                ? *(const float4*)(src + (size_t)node * stride + kloc + qofs)
                : make_float4(0.f, 0.f, 0.f, 0.f);
        }
    };
    auto sts_tile = [&](int buf, const float4* v) {
        float* dst = smem + buf * BUFW;
#pragma unroll
        for (int pass = 0; pass < 4; ++pass)
            *(float4*)(dst + (pass * 64 + srow) * XPAD + qofs) = v[pass];
    };

    u64 accA[4], accB[4];
#pragma unroll
    for (int p = 0; p < 4; ++p) { accA[p] = 0ull; accB[p] = 0ull; }

    // prologue: tile0 staged to buf0, tile1 held in regs
    float4 vr[4];
    ldg_tile(0, vr);
    sts_tile(0, vr);
    ldg_tile(1, vr);
    __syncthreads();

    for (int tile = 0; tile < NTILES; ++tile) {
        // store tile+1 (into the buffer NOT being computed), prefetch tile+2
        if (tile + 1 < NTILES) {
            sts_tile((tile + 1) & 1, vr);
            if (tile + 2 < NTILES) ldg_tile(tile + 2, vr);
        }

        const float* xbuf = smem + (tile & 1) * BUFW;
        const float* wbas = ws + tile * KT * 16 + jh * 8;
#pragma unroll
        for (int kk = 0; kk < KT; kk += 4) {
            float4 xa = *(const float4*)(xbuf + row0 * XPAD + kk);
            float4 xb = *(const float4*)(xbuf + (row0 + 128) * XPAD + kk);
#pragma unroll
            for (int r = 0; r < 4; ++r) {
                const ulonglong2* wr = (const ulonglong2*)(wbas + (kk + r) * 16);
                ulonglong2 q = wr[0];          // j 0..3 of this half
                ulonglong2 p = wr[1];          // j 4..7 of this half
                float fa = (r == 0) ? xa.x : (r == 1) ? xa.y : (r == 2) ? xa.z : xa.w;
                float fb = (r == 0) ? xb.x : (r == 1) ? xb.y : (r == 2) ? xb.z : xb.w;
                u64 va = pk2(fa), vb = pk2(fb);
                ffma2(accA[0], va, q.x); ffma2(accA[1], va, q.y);
                ffma2(accA[2], va, p.x); ffma2(accA[3], va, p.y);
                ffma2(accB[0], vb, q.x); ffma2(accB[1], vb, q.y);
                ffma2(accB[2], vb, p.x); ffma2(accB[3], vb, p.y);
            }
        }
        __syncthreads();
    }

    // --- epilogue: bias + relu + W2 dot (per j-half), cross-half reduce ---
    float w2r[8], b1r[8];
#pragma unroll
    for (int j = 0; j < 8; ++j) { b1r[j] = b1[jh * 8 + j]; w2r[j] = W2[jh * 8 + j]; }

    float part[2];
#pragma unroll
    for (int n = 0; n < 2; ++n) {
        u64* acc = n ? accB : accA;
        float s = 0.f;
#pragma unroll
        for (int p = 0; p < 4; ++p) {
            float2 a = upk(acc[p]);
            s += fmaxf(a.x + b1r[2 * p],     0.f) * w2r[2 * p];
            s += fmaxf(a.y + b1r[2 * p + 1], 0.f) * w2r[2 * p + 1];
        }
        part[n] = s;
    }

    float* red = smem;   // reuse x buffers
    if (jh == 1) { red[row0] = part[0]; red[row0 + 128] = part[1]; }
    __syncthreads();
    if (jh == 0) {
        const float bias2 = b2[0];
#pragma unroll
        for (int n = 0; n < 2; ++n) {
            int node = base + row0 + n * 128;
            if (node < N) {
                float o = part[n] + red[row0 + n * 128] + bias2;
                int seg = segids[node];
                atomicAdd(&g_sum[seg], o);
                atomicAdd(&g_cnt[seg], 1.f);
                unsigned b = __float_as_uint(o);
                unsigned e = (b & 0x80000000u) ? ~b : (b | 0x80000000u);
                atomicMax(&g_max[seg], e);
            }
        }
    }

    // --- last block finalizes ---
    __threadfence();
    __shared__ unsigned s_last;
    if (t == 0) s_last = (atomicAdd(&g_done, 1) == (unsigned)(grid - 1)) ? 1u : 0u;
    __syncthreads();
    if (s_last) {
#pragma unroll
        for (int i = 0; i < NSEG / BLOCK; ++i) {
            int s = t + i * BLOCK;
            float sum = __ldcg(&g_sum[s]);
            float cnt = __ldcg(&g_cnt[s]);
            unsigned u = __ldcg(&g_max[s]);
            float mean = sum / fmaxf(cnt, 1.f);
            float mx = (u & 0x80000000u) ? __uint_as_float(u ^ 0x80000000u)
                                         : __uint_as_float(~u);
            out[s] = mx * 0.5f + mean * 0.5f;
            g_sum[s] = 0.f; g_cnt[s] = 0.f; g_max[s] = 0u;
        }
        __threadfence();
        if (t == 0) g_done = 0;
    }
}

extern "C" void kernel_launch(void* const* d_in, const int* in_sizes, int n_in,
                              void* d_out, int out_size) {
    const float* nodes  = (const float*)d_in[0];
    const float* goal   = (const float*)d_in[1];
    const int*   segids = (const int*)d_in[2];
    int iW = (in_sizes[3] == INDIM * 16) ? 3 : 4;   // num_segments may be absent
    const float* W1 = (const float*)d_in[iW];
    const float* b1 = (const float*)d_in[iW + 1];
    const float* W2 = (const float*)d_in[iW + 2];
    const float* b2 = (const float*)d_in[iW + 3];
    const int N = in_sizes[2];

    cudaFuncSetAttribute(mlp_seg_kernel,
                         cudaFuncAttributeMaxDynamicSharedMemorySize, SMEM_BYTES);
    int grid = (N + MROWS - 1) / MROWS;
    mlp_seg_kernel<<<grid, BLOCK, SMEM_BYTES>>>(nodes, goal, segids,
                                                W1, b1, W2, b2,
                                                (float*)d_out, N, grid);
}

// round 9
// speedup vs baseline: 1.1179x; 1.1179x over previous
#include <cuda_runtime.h>
#include <cstdint>

#define NSEG   512
#define HID    512
#define GOALD  128
#define INDIM  640
#define BLOCK  256
#define MROWS  512          // nodes per block (2 per thread)
#define KT     32           // k tile (floats) = 128 B -> full-line LDGs
#define XPAD   36           // padded row stride (words): conflict-free LDS/STS
#define NTILES (INDIM / KT) // 20
#define BUFW   (MROWS * XPAD)
#define WS_OFF (2 * BUFW)
#define SMEM_BYTES ((2 * BUFW + INDIM * 16) * 4)   // 184 KB

typedef unsigned long long u64;

__device__ float    g_sum[NSEG];
__device__ float    g_cnt[NSEG];
__device__ unsigned g_max[NSEG];
__device__ unsigned g_done;

__device__ __forceinline__ void ffma2(u64 &acc, u64 a, u64 b) {
    asm("fma.rn.f32x2 %0, %1, %2, %0;" : "+l"(acc) : "l"(a), "l"(b));
}
__device__ __forceinline__ u64 pk2(float v) {
    u64 r; asm("mov.b64 %0, {%1, %1};" : "=l"(r) : "f"(v)); return r;
}
__device__ __forceinline__ float2 upk(u64 v) {
    float2 f; asm("mov.b64 {%0, %1}, %2;" : "=f"(f.x), "=f"(f.y) : "l"(v)); return f;
}

__global__ __launch_bounds__(BLOCK, 1) void mlp_seg_kernel(
    const float* __restrict__ nodes, const float* __restrict__ goal,
    const int* __restrict__ segids,
    const float* __restrict__ W1, const float* __restrict__ b1,
    const float* __restrict__ W2, const float* __restrict__ b2,
    float* __restrict__ out, int N, int grid)
{
    extern __shared__ float smem[];
    float* ws = smem + WS_OFF;           // [INDIM][16]
    const int t    = threadIdx.x;
    const int base = blockIdx.x * MROWS;

    // --- preload full W1 (10240 floats, coalesced) ---
#pragma unroll
    for (int p = 0; p < INDIM * 16 / 4 / BLOCK; ++p)
        ((float4*)ws)[p * BLOCK + t] = ((const float4*)W1)[p * BLOCK + t];

    // --- staging: 512 rows x 128B per tile; task = i*256+t ---
    // row = task>>3 (consecutive across lanes), chunk = task&7 (16B units)
    // LDG: 32 lanes cover 4 full 128B lines contiguously. STS conflict-free.
    auto ldg_tile = [&](int tile, float4* v) {
        const int k0 = tile * KT;
        const float* src; int stride, kloc;
        if (k0 < HID) { src = nodes; stride = HID;   kloc = k0; }
        else          { src = goal;  stride = GOALD; kloc = k0 - HID; }
#pragma unroll
        for (int i = 0; i < 16; ++i) {
            int task = i * BLOCK + t;
            int row  = task >> 3, ch = task & 7;
            int node = base + row;
            v[i] = (node < N)
                ? *(const float4*)(src + (size_t)node * stride + kloc + ch * 4)
                : make_float4(0.f, 0.f, 0.f, 0.f);
        }
    };
    auto sts_tile = [&](int buf, const float4* v) {
        float* dst = smem + buf * BUFW;
#pragma unroll
        for (int i = 0; i < 16; ++i) {
            int task = i * BLOCK + t;
            int row  = task >> 3, ch = task & 7;
            *(float4*)(dst + row * XPAD + ch * 4) = v[i];
        }
    };

    u64 accA[8], accB[8];
#pragma unroll
    for (int p = 0; p < 8; ++p) { accA[p] = 0ull; accB[p] = 0ull; }

    // prologue
    float4 vr[16];
    ldg_tile(0, vr);
    sts_tile(0, vr);
    __syncthreads();

#pragma unroll 1
    for (int tile = 0; tile < NTILES; ++tile) {
        // issue next tile's LDGs now; latency hides under compute
        if (tile + 1 < NTILES) ldg_tile(tile + 1, vr);

        const float* xbuf = smem + (tile & 1) * BUFW;
        const float* wtil = ws + tile * KT * 16;
#pragma unroll
        for (int kk = 0; kk < KT; kk += 4) {
            float4 xa = *(const float4*)(xbuf + t * XPAD + kk);
            float4 xb = *(const float4*)(xbuf + (t + 256) * XPAD + kk);
#pragma unroll
            for (int r = 0; r < 4; ++r) {
                const ulonglong2* wr = (const ulonglong2*)(wtil + (kk + r) * 16);
                ulonglong2 w0 = wr[0], w1 = wr[1], w2 = wr[2], w3 = wr[3];
                float fa = (r == 0) ? xa.x : (r == 1) ? xa.y : (r == 2) ? xa.z : xa.w;
                float fb = (r == 0) ? xb.x : (r == 1) ? xb.y : (r == 2) ? xb.z : xb.w;
                u64 va = pk2(fa), vb = pk2(fb);
                ffma2(accA[0], va, w0.x); ffma2(accA[1], va, w0.y);
                ffma2(accA[2], va, w1.x); ffma2(accA[3], va, w1.y);
                ffma2(accA[4], va, w2.x); ffma2(accA[5], va, w2.y);
                ffma2(accA[6], va, w3.x); ffma2(accA[7], va, w3.y);
                ffma2(accB[0], vb, w0.x); ffma2(accB[1], vb, w0.y);
                ffma2(accB[2], vb, w1.x); ffma2(accB[3], vb, w1.y);
                ffma2(accB[4], vb, w2.x); ffma2(accB[5], vb, w2.y);
                ffma2(accB[6], vb, w3.x); ffma2(accB[7], vb, w3.y);
            }
        }
        // store next tile into the other buffer (safe: compute used buf tile&1)
        if (tile + 1 < NTILES) sts_tile((tile + 1) & 1, vr);
        __syncthreads();
    }

    // --- epilogue: this thread owns ALL 16 j for rows t and t+256 ---
    float w2r[16], b1r[16];
#pragma unroll
    for (int j = 0; j < 16; ++j) { b1r[j] = b1[j]; w2r[j] = W2[j]; }
    const float bias2 = b2[0];

#pragma unroll
    for (int n = 0; n < 2; ++n) {
        u64* acc = n ? accB : accA;
        int node = base + t + n * 256;
        if (node < N) {
            float o = bias2;
#pragma unroll
            for (int p = 0; p < 8; ++p) {
                float2 a = upk(acc[p]);
                o += fmaxf(a.x + b1r[2 * p],     0.f) * w2r[2 * p];
                o += fmaxf(a.y + b1r[2 * p + 1], 0.f) * w2r[2 * p + 1];
            }
            int seg = segids[node];
            atomicAdd(&g_sum[seg], o);
            atomicAdd(&g_cnt[seg], 1.f);
            unsigned b = __float_as_uint(o);
            unsigned e = (b & 0x80000000u) ? ~b : (b | 0x80000000u);
            atomicMax(&g_max[seg], e);
        }
    }

    // --- last block finalizes ---
    __threadfence();
    __shared__ unsigned s_last;
    if (t == 0) s_last = (atomicAdd(&g_done, 1) == (unsigned)(grid - 1)) ? 1u : 0u;
    __syncthreads();
    if (s_last) {
#pragma unroll
        for (int i = 0; i < NSEG / BLOCK; ++i) {
            int s = t + i * BLOCK;
            float sum = __ldcg(&g_sum[s]);
            float cnt = __ldcg(&g_cnt[s]);
            unsigned u = __ldcg(&g_max[s]);
            float mean = sum / fmaxf(cnt, 1.f);
            float mx = (u & 0x80000000u) ? __uint_as_float(u ^ 0x80000000u)
                                         : __uint_as_float(~u);
            out[s] = mx * 0.5f + mean * 0.5f;
            g_sum[s] = 0.f; g_cnt[s] = 0.f; g_max[s] = 0u;
        }
        __threadfence();
        if (t == 0) g_done = 0;
    }
}

extern "C" void kernel_launch(void* const* d_in, const int* in_sizes, int n_in,
                              void* d_out, int out_size) {
    const float* nodes  = (const float*)d_in[0];
    const float* goal   = (const float*)d_in[1];
    const int*   segids = (const int*)d_in[2];
    int iW = (in_sizes[3] == INDIM * 16) ? 3 : 4;   // num_segments may be absent
    const float* W1 = (const float*)d_in[iW];
    const float* b1 = (const float*)d_in[iW + 1];
    const float* W2 = (const float*)d_in[iW + 2];
    const float* b2 = (const float*)d_in[iW + 3];
    const int N = in_sizes[2];

    cudaFuncSetAttribute(mlp_seg_kernel,
                         cudaFuncAttributeMaxDynamicSharedMemorySize, SMEM_BYTES);
    int grid = (N + MROWS - 1) / MROWS;
    mlp_seg_kernel<<<grid, BLOCK, SMEM_BYTES>>>(nodes, goal, segids,
                                                W1, b1, W2, b2,
                                                (float*)d_out, N, grid);
}

// round 10
// speedup vs baseline: 1.2356x; 1.1052x over previous
#include <cuda_runtime.h>
#include <cstdint>

#define NSEG   512
#define HID    512
#define GOALD  128
#define INDIM  640
#define BLOCK  512
#define MROWS  1024         // nodes per block (2 per thread)
#define KT     32           // k tile (floats) = 128 B -> full-line LDGs
#define XPAD   36           // padded row stride (words): conflict-free LDS/STS
#define NTILES (INDIM / KT) // 20
#define BUFW   (MROWS * XPAD)
#define WS_OFF BUFW
#define SMEM_BYTES ((BUFW + INDIM * 16) * 4)   // ~187 KB

typedef unsigned long long u64;

__device__ float    g_sum[NSEG];
__device__ float    g_cnt[NSEG];
__device__ unsigned g_max[NSEG];
__device__ unsigned g_done;

__device__ __forceinline__ void ffma2(u64 &acc, u64 a, u64 b) {
    asm("fma.rn.f32x2 %0, %1, %2, %0;" : "+l"(acc) : "l"(a), "l"(b));
}
__device__ __forceinline__ u64 pk2(float v) {
    u64 r; asm("mov.b64 %0, {%1, %1};" : "=l"(r) : "f"(v)); return r;
}
__device__ __forceinline__ float2 upk(u64 v) {
    float2 f; asm("mov.b64 {%0, %1}, %2;" : "=f"(f.x), "=f"(f.y) : "l"(v)); return f;
}

__global__ __launch_bounds__(BLOCK, 1) void mlp_seg_kernel(
    const float* __restrict__ nodes, const float* __restrict__ goal,
    const int* __restrict__ segids,
    const float* __restrict__ W1, const float* __restrict__ b1,
    const float* __restrict__ W2, const float* __restrict__ b2,
    float* __restrict__ out, int N, int grid)
{
    extern __shared__ float smem[];
    float* ws = smem + WS_OFF;           // [INDIM][16]
    const int t    = threadIdx.x;
    const int base = blockIdx.x * MROWS;

    // --- preload full W1 (10240 floats, coalesced) ---
#pragma unroll
    for (int p = 0; p < INDIM * 16 / 4 / BLOCK; ++p)
        ((float4*)ws)[p * BLOCK + t] = ((const float4*)W1)[p * BLOCK + t];

    // --- staging: 1024 rows x 128B per tile; task = i*512+t ---
    // row = task>>3 (4 consecutive rows per warp), chunk = task&7 (16B units)
    // LDG: each warp instr covers 4 full 128B lines. STS conflict-free (XPAD=36).
    auto ldg_tile = [&](int tile, float4* v) {
        const int k0 = tile * KT;
        const float* src; int stride, kloc;
        if (k0 < HID) { src = nodes; stride = HID;   kloc = k0; }
        else          { src = goal;  stride = GOALD; kloc = k0 - HID; }
#pragma unroll
        for (int i = 0; i < 16; ++i) {
            int task = i * BLOCK + t;
            int row  = task >> 3, ch = task & 7;
            int node = base + row;
            v[i] = (node < N)
                ? *(const float4*)(src + (size_t)node * stride + kloc + ch * 4)
                : make_float4(0.f, 0.f, 0.f, 0.f);
        }
    };
    auto sts_tile = [&](const float4* v) {
#pragma unroll
        for (int i = 0; i < 16; ++i) {
            int task = i * BLOCK + t;
            int row  = task >> 3, ch = task & 7;
            *(float4*)(smem + row * XPAD + ch * 4) = v[i];
        }
    };

    u64 accA[8], accB[8];
#pragma unroll
    for (int p = 0; p < 8; ++p) { accA[p] = 0ull; accB[p] = 0ull; }

    // prologue: tile 0 staged
    float4 vr[16];
    ldg_tile(0, vr);
    sts_tile(vr);
    __syncthreads();

#pragma unroll 1
    for (int tile = 0; tile < NTILES; ++tile) {
        // issue next tile's LDGs now; latency hides under compute
        if (tile + 1 < NTILES) ldg_tile(tile + 1, vr);

        const float* wtil = ws + tile * KT * 16;
#pragma unroll
        for (int kk = 0; kk < KT; kk += 4) {
            float4 xa = *(const float4*)(smem + t * XPAD + kk);
            float4 xb = *(const float4*)(smem + (t + BLOCK) * XPAD + kk);
#pragma unroll
            for (int r = 0; r < 4; ++r) {
                const ulonglong2* wr = (const ulonglong2*)(wtil + (kk + r) * 16);
                ulonglong2 w0 = wr[0], w1 = wr[1], w2 = wr[2], w3 = wr[3];
                float fa = (r == 0) ? xa.x : (r == 1) ? xa.y : (r == 2) ? xa.z : xa.w;
                float fb = (r == 0) ? xb.x : (r == 1) ? xb.y : (r == 2) ? xb.z : xb.w;
                u64 va = pk2(fa), vb = pk2(fb);
                ffma2(accA[0], va, w0.x); ffma2(accA[1], va, w0.y);
                ffma2(accA[2], va, w1.x); ffma2(accA[3], va, w1.y);
                ffma2(accA[4], va, w2.x); ffma2(accA[5], va, w2.y);
                ffma2(accA[6], va, w3.x); ffma2(accA[7], va, w3.y);
                ffma2(accB[0], vb, w0.x); ffma2(accB[1], vb, w0.y);
                ffma2(accB[2], vb, w1.x); ffma2(accB[3], vb, w1.y);
                ffma2(accB[4], vb, w2.x); ffma2(accB[5], vb, w2.y);
                ffma2(accB[6], vb, w3.x); ffma2(accB[7], vb, w3.y);
            }
        }
        __syncthreads();                 // everyone done reading tile
        if (tile + 1 < NTILES) {
            sts_tile(vr);                // overwrite single buffer
            __syncthreads();
        }
    }

    // --- epilogue: thread owns ALL 16 j for rows t and t+512 ---
    float w2r[16], b1r[16];
#pragma unroll
    for (int j = 0; j < 16; ++j) { b1r[j] = b1[j]; w2r[j] = W2[j]; }
    const float bias2 = b2[0];

#pragma unroll
    for (int n = 0; n < 2; ++n) {
        u64* acc = n ? accB : accA;
        int node = base + t + n * BLOCK;
        if (node < N) {
            float o = bias2;
#pragma unroll
            for (int p = 0; p < 8; ++p) {
                float2 a = upk(acc[p]);
                o += fmaxf(a.x + b1r[2 * p],     0.f) * w2r[2 * p];
                o += fmaxf(a.y + b1r[2 * p + 1], 0.f) * w2r[2 * p + 1];
            }
            int seg = segids[node];
            atomicAdd(&g_sum[seg], o);
            atomicAdd(&g_cnt[seg], 1.f);
            unsigned b = __float_as_uint(o);
            unsigned e = (b & 0x80000000u) ? ~b : (b | 0x80000000u);
            atomicMax(&g_max[seg], e);
        }
    }

    // --- last block finalizes ---
    __threadfence();
    __shared__ unsigned s_last;
    if (t == 0) s_last = (atomicAdd(&g_done, 1) == (unsigned)(grid - 1)) ? 1u : 0u;
    __syncthreads();
    if (s_last && t < NSEG) {
        float sum = __ldcg(&g_sum[t]);
        float cnt = __ldcg(&g_cnt[t]);
        unsigned u = __ldcg(&g_max[t]);
        float mean = sum / fmaxf(cnt, 1.f);
        float mx = (u & 0x80000000u) ? __uint_as_float(u ^ 0x80000000u)
                                     : __uint_as_float(~u);
        out[t] = mx * 0.5f + mean * 0.5f;
        g_sum[t] = 0.f; g_cnt[t] = 0.f; g_max[t] = 0u;
        __threadfence();
        if (t == 0) g_done = 0;
    }
}

extern "C" void kernel_launch(void* const* d_in, const int* in_sizes, int n_in,
                              void* d_out, int out_size) {
    const float* nodes  = (const float*)d_in[0];
    const float* goal   = (const float*)d_in[1];
    const int*   segids = (const int*)d_in[2];
    int iW = (in_sizes[3] == INDIM * 16) ? 3 : 4;   // num_segments may be absent
    const float* W1 = (const float*)d_in[iW];
    const float* b1 = (const float*)d_in[iW + 1];
    const float* W2 = (const float*)d_in[iW + 2];
    const float* b2 = (const float*)d_in[iW + 3];
    const int N = in_sizes[2];

    cudaFuncSetAttribute(mlp_seg_kernel,
                         cudaFuncAttributeMaxDynamicSharedMemorySize, SMEM_BYTES);
    int grid = (N + MROWS - 1) / MROWS;
    mlp_seg_kernel<<<grid, BLOCK, SMEM_BYTES>>>(nodes, goal, segids,
                                                W1, b1, W2, b2,
                                                (float*)d_out, N, grid);
}

// round 16
// speedup vs baseline: 1.3074x; 1.0581x over previous
#include <cuda_runtime.h>
#include <cstdint>

#define NSEG   512
#define HID    512
#define GOALD  128
#define INDIM  640
#define BLOCK  256
#define MROWS  512          // nodes per block (2 per thread)
#define KT     32           // k tile (floats) = 128B rows, full-line traffic
#define NTILES (INDIM / KT) // 20
#define XTILE_B  (MROWS * 128)           // 64 KB per x stage
#define WTILE_B  (KT * 16 * 4)           // 2 KB per W stage
#define OFF_X    0
#define OFF_W    (2 * XTILE_B)           // after 2-slot x ring
#define SMEM_BYTES (2 * XTILE_B + 2 * WTILE_B)   // 135168 B

typedef unsigned long long u64;

__device__ float    g_sum[NSEG];
__device__ float    g_cnt[NSEG];
__device__ unsigned g_max[NSEG];
__device__ unsigned g_done;

__device__ __forceinline__ void ffma2(u64 &acc, u64 a, u64 b) {
    asm("fma.rn.f32x2 %0, %1, %2, %0;" : "+l"(acc) : "l"(a), "l"(b));
}
__device__ __forceinline__ u64 pk2(float v) {
    u64 r; asm("mov.b64 %0, {%1, %1};" : "=l"(r) : "f"(v)); return r;
}
__device__ __forceinline__ float2 upk(u64 v) {
    float2 f; asm("mov.b64 {%0, %1}, %2;" : "=f"(f.x), "=f"(f.y) : "l"(v)); return f;
}
__device__ __forceinline__ void cp16(uint32_t dst, const void* src, bool pred) {
    int sz = pred ? 16 : 0;   // src_size 0 -> zero-fill
    asm volatile("cp.async.cg.shared.global [%0], [%1], 16, %2;"
                 :: "r"(dst), "l"(src), "r"(sz));
}
__device__ __forceinline__ void cp_commit() { asm volatile("cp.async.commit_group;"); }
template <int M> __device__ __forceinline__ void cp_wait() {
    asm volatile("cp.async.wait_group %0;" :: "n"(M));
}

__global__ __launch_bounds__(BLOCK, 1) void mlp_seg_kernel(
    const float* __restrict__ nodes, const float* __restrict__ goal,
    const int* __restrict__ segids,
    const float* __restrict__ W1, const float* __restrict__ b1,
    const float* __restrict__ W2, const float* __restrict__ b2,
    float* __restrict__ out, int N, int grid)
{
    extern __shared__ float smem[];
    const uint32_t sb = (uint32_t)__cvta_generic_to_shared(smem);
    const int t    = threadIdx.x;
    const int base = blockIdx.x * MROWS;

    // ---- staging: x tile (512 rows x 128B, dense + XOR swizzle) + W tile ----
    // task = i*256+t : row = task>>3, ch = task&7 ; phys chunk = ch ^ (row&7)
    auto stage = [&](int tile) {
        const int k0 = tile * KT;
        const float* src; int stride, kloc;
        if (k0 < HID) { src = nodes; stride = HID;   kloc = k0; }
        else          { src = goal;  stride = GOALD; kloc = k0 - HID; }
        uint32_t xb = sb + OFF_X + (tile & 1) * XTILE_B;
#pragma unroll
        for (int i = 0; i < 16; ++i) {
            int task = i * BLOCK + t;
            int row  = task >> 3, ch = task & 7;
            int node = base + row;
            cp16(xb + (uint32_t)(row * 128 + ((ch ^ (row & 7)) << 4)),
                 src + (size_t)node * stride + kloc + ch * 4, node < N);
        }
        if (t < 128)
            cp16(sb + OFF_W + (tile & 1) * WTILE_B + t * 16,
                 W1 + k0 * 16 + t * 4, true);
        cp_commit();
    };

    u64 accA[8], accB[8];
#pragma unroll
    for (int p = 0; p < 8; ++p) { accA[p] = 0ull; accB[p] = 0ull; }

    stage(0);
    stage(1);

    const int xsw = (t & 7) << 2;        // row-swizzle key in float units
    const float* xrowA = smem + t * 32;              // logical row t
    const float* xrowB = smem + (t + BLOCK) * 32;    // logical row t+256 (same &7)

#pragma unroll 1
    for (int tile = 0; tile < NTILES; ++tile) {
        if (tile == NTILES - 1) cp_wait<0>();   // final tile: drain fully
        else                    cp_wait<1>();   // tile's data arrived
        __syncthreads();

        const int   boff = (tile & 1) * (XTILE_B / 4);
        const float* wtil = smem + OFF_W / 4 + (tile & 1) * (WTILE_B / 4);
#pragma unroll
        for (int kk = 0; kk < KT; kk += 4) {
            int ph = kk ^ xsw;           // ((kk>>2)^(t&7))*4 in float units
            float4 xa = *(const float4*)(xrowA + boff + ph);
            float4 xb = *(const float4*)(xrowB + boff + ph);
#pragma unroll
            for (int r = 0; r < 4; ++r) {
                const ulonglong2* wr = (const ulonglong2*)(wtil + (kk + r) * 16);
                ulonglong2 w0 = wr[0], w1 = wr[1], w2 = wr[2], w3 = wr[3];
                float fa = (r == 0) ? xa.x : (r == 1) ? xa.y : (r == 2) ? xa.z : xa.w;
                float fb = (r == 0) ? xb.x : (r == 1) ? xb.y : (r == 2) ? xb.z : xb.w;
                u64 va = pk2(fa), vb = pk2(fb);
                ffma2(accA[0], va, w0.x); ffma2(accA[1], va, w0.y);
                ffma2(accA[2], va, w1.x); ffma2(accA[3], va, w1.y);
                ffma2(accA[4], va, w2.x); ffma2(accA[5], va, w2.y);
                ffma2(accA[6], va, w3.x); ffma2(accA[7], va, w3.y);
                ffma2(accB[0], vb, w0.x); ffma2(accB[1], vb, w0.y);
                ffma2(accB[2], vb, w1.x); ffma2(accB[3], vb, w1.y);
                ffma2(accB[4], vb, w2.x); ffma2(accB[5], vb, w2.y);
                ffma2(accB[6], vb, w3.x); ffma2(accB[7], vb, w3.y);
            }
        }
        __syncthreads();                 // all warps done reading this slot
        if (tile + 2 < NTILES) stage(tile + 2);   // refill it (async, overlaps)
    }

    // --- epilogue: thread owns ALL 16 j for rows t and t+256 ---
    float w2r[16], b1r[16];
#pragma unroll
    for (int j = 0; j < 16; ++j) { b1r[j] = b1[j]; w2r[j] = W2[j]; }
    const float bias2 = b2[0];

#pragma unroll
    for (int n = 0; n < 2; ++n) {
        u64* acc = n ? accB : accA;
        int node = base + t + n * BLOCK;
        if (node < N) {
            float o = bias2;
#pragma unroll
            for (int p = 0; p < 8; ++p) {
                float2 a = upk(acc[p]);
                o += fmaxf(a.x + b1r[2 * p],     0.f) * w2r[2 * p];
                o += fmaxf(a.y + b1r[2 * p + 1], 0.f) * w2r[2 * p + 1];
            }
            int seg = segids[node];
            atomicAdd(&g_sum[seg], o);
            atomicAdd(&g_cnt[seg], 1.f);
            unsigned b = __float_as_uint(o);
            unsigned e = (b & 0x80000000u) ? ~b : (b | 0x80000000u);
            atomicMax(&g_max[seg], e);
        }
    }

    // --- last block finalizes ---
    __threadfence();
    __shared__ unsigned s_last;
    if (t == 0) s_last = (atomicAdd(&g_done, 1) == (unsigned)(grid - 1)) ? 1u : 0u;
    __syncthreads();
    if (s_last) {
#pragma unroll
        for (int i = 0; i < NSEG / BLOCK; ++i) {
            int s = t + i * BLOCK;
            float sum = __ldcg(&g_sum[s]);
            float cnt = __ldcg(&g_cnt[s]);
            unsigned u = __ldcg(&g_max[s]);
            float mean = sum / fmaxf(cnt, 1.f);
            float mx = (u & 0x80000000u) ? __uint_as_float(u ^ 0x80000000u)
                                         : __uint_as_float(~u);
            out[s] = mx * 0.5f + mean * 0.5f;
            g_sum[s] = 0.f; g_cnt[s] = 0.f; g_max[s] = 0u;
        }
        __threadfence();
        if (t == 0) g_done = 0;
    }
}

extern "C" void kernel_launch(void* const* d_in, const int* in_sizes, int n_in,
                              void* d_out, int out_size) {
    const float* nodes  = (const float*)d_in[0];
    const float* goal   = (const float*)d_in[1];
    const int*   segids = (const int*)d_in[2];
    int iW = (in_sizes[3] == INDIM * 16) ? 3 : 4;   // num_segments may be absent
    const float* W1 = (const float*)d_in[iW];
    const float* b1 = (const float*)d_in[iW + 1];
    const float* W2 = (const float*)d_in[iW + 2];
    const float* b2 = (const float*)d_in[iW + 3];
    const int N = in_sizes[2];

    cudaFuncSetAttribute(mlp_seg_kernel,
                         cudaFuncAttributeMaxDynamicSharedMemorySize, SMEM_BYTES);
    int grid = (N + MROWS - 1) / MROWS;
    mlp_seg_kernel<<<grid, BLOCK, SMEM_BYTES>>>(nodes, goal, segids,
                                                W1, b1, W2, b2,
                                                (float*)d_out, N, grid);
}